// round 5
// baseline (speedup 1.0000x reference)
#include <cuda_runtime.h>
#include <math.h>

#define Bz 64
#define Tz 512
#define Hz 1024
#define H2z 2048
#define NCTA 128

typedef unsigned long long ull;

// Scratch (__device__ globals; no allocation allowed)
__device__ float g_xw[(size_t)32768 * 1024];   // [B*T, H]
__device__ float g_h[Bz * Hz];
__device__ float g_hrnn[Bz * Hz];
__device__ float g_p1[32 * Bz * Hz];           // 32 k-slices
__device__ float g_p2[16 * Bz * H2z];          // 16 k-slices
__device__ float g_lpp[Bz][2];
__device__ unsigned g_flags[NCTA];
__device__ unsigned g_epoch;

__device__ __forceinline__ ull dup2(float a) {
    ull r; asm("mov.b64 %0,{%1,%1};" : "=l"(r) : "f"(a)); return r;
}
__device__ __forceinline__ void fma2(ull& acc, ull a, ull w) {
    asm("fma.rn.f32x2 %0,%1,%2,%0;" : "+l"(acc) : "l"(a), "l"(w));
}

// Flag-array grid barrier, persistent epoch (replay-safe, flags never reset)
__device__ __forceinline__ void grid_sync(unsigned& gen) {
    __syncthreads();
    gen++;
    if (threadIdx.x == 0)
        asm volatile("st.release.gpu.u32 [%0], %1;"
                     :: "l"(&g_flags[blockIdx.x]), "r"(gen) : "memory");
    if (threadIdx.x < NCTA) {
        unsigned v;
        do {
            asm volatile("ld.acquire.gpu.u32 %0, [%1];"
                         : "=r"(v) : "l"(&g_flags[threadIdx.x]) : "memory");
        } while ((int)(v - gen) < 0);
    }
    __syncthreads();
}

// Persistent-kernel SMEM: weights resident + duplicated-A staging
struct SmemR {
    ull   As2[64][66];      // A, each value duplicated into both f32x2 halves
    float Ws1[32][260];     // w_hh slice, transposed [k][n]
    float Ws2[64][260];     // w_g  slice, transposed [k][n]
    float red[8];
};

// Stage A[64][kwords] from global (L2) into As2, duplicated.
__device__ __forceinline__ void stage_A(ull (*As2)[66],
    const float* __restrict__ A, int kb, int kwords, int tid)
{
    const int ar  = tid >> 2;                 // 4 threads per row
    const int ac0 = (tid & 3) * (kwords / 4);
    #pragma unroll
    for (int c = 0; c < 16; c += 4) {
        if (c >= kwords / 4) break;
        float4 v = __ldcg((const float4*)&A[ar * 1024 + kb + ac0 + c]);
        As2[ar][ac0 + c + 0] = dup2(v.x);
        As2[ar][ac0 + c + 1] = dup2(v.y);
        As2[ar][ac0 + c + 2] = dup2(v.z);
        As2[ar][ac0 + c + 3] = dup2(v.w);
    }
}

// 64x256 tile, 8 rows x 8 cols per thread, weights + A in SMEM.
__device__ __forceinline__ void gemm8x8(const ull (*As2)[66],
    const float (*Ws)[260], int kcnt, ull acc[8][4], int tx8, int ty8)
{
    #pragma unroll 4
    for (int k = 0; k < kcnt; k += 2) {
        ull a0[8], a1[8];
        #pragma unroll
        for (int i = 0; i < 8; i++) {
            ulonglong2 av = *(const ulonglong2*)&As2[ty8 + i][k];
            a0[i] = av.x; a1[i] = av.y;
        }
        {
            ulonglong2 w0 = *(const ulonglong2*)&Ws[k][tx8];
            ulonglong2 w1 = *(const ulonglong2*)&Ws[k][tx8 + 4];
            #pragma unroll
            for (int i = 0; i < 8; i++) {
                fma2(acc[i][0], a0[i], w0.x);
                fma2(acc[i][1], a0[i], w0.y);
                fma2(acc[i][2], a0[i], w1.x);
                fma2(acc[i][3], a0[i], w1.y);
            }
        }
        {
            ulonglong2 w0 = *(const ulonglong2*)&Ws[k + 1][tx8];
            ulonglong2 w1 = *(const ulonglong2*)&Ws[k + 1][tx8 + 4];
            #pragma unroll
            for (int i = 0; i < 8; i++) {
                fma2(acc[i][0], a1[i], w0.x);
                fma2(acc[i][1], a1[i], w0.y);
                fma2(acc[i][2], a1[i], w1.x);
                fma2(acc[i][3], a1[i], w1.y);
            }
        }
    }
}

__device__ __forceinline__ void store8x8(float* __restrict__ Cp, int ldC,
                                         int n0, ull acc[8][4], int tx8, int ty8)
{
    #pragma unroll
    for (int i = 0; i < 8; i++) {
        int b = ty8 + i;
        *(ulonglong2*)&Cp[(size_t)b * ldC + n0 + tx8] =
            make_ulonglong2(acc[i][0], acc[i][1]);
        *(ulonglong2*)&Cp[(size_t)b * ldC + n0 + tx8 + 4] =
            make_ulonglong2(acc[i][2], acc[i][3]);
    }
}

// ---------------------------------------------------------------------------
// Precompute GEMM (unchanged from R3 design): g_xw = x @ w_ih^T + b_ih + b_hh
// ---------------------------------------------------------------------------
struct SmemX {
    float As[64][36];
    float Ws[32][258];
};

__global__ __launch_bounds__(512) void xw_kernel(
    const float* __restrict__ x, const float* __restrict__ w_ih,
    const float* __restrict__ b_ih, const float* __restrict__ b_hh)
{
    __shared__ SmemX s;
    const int n0 = blockIdx.x * 256;
    const int m0 = blockIdx.y * 64;
    const int tid = threadIdx.x;
    const int tx = tid & 31;
    const int ty4 = (tid >> 5) << 2;
    const int ar = tid >> 3;
    const int ac = (tid & 7) << 2;
    ull acc[4][4] = {};

    const float* A = x + (size_t)m0 * 1024;
    const float* W = w_ih + (size_t)n0 * 1024;
    for (int k0 = 0; k0 < 1024; k0 += 32) {
        float4 v = __ldg((const float4*)&A[ar * 1024 + k0 + ac]);
        *(float4*)&s.As[ar][ac] = v;
        #pragma unroll
        for (int i = 0; i < 16; i++) {
            int e = tid + i * 512;
            int n = e >> 5, kk = e & 31;
            s.Ws[kk][n] = __ldg(&W[n * 1024 + k0 + kk]);
        }
        __syncthreads();
        #pragma unroll
        for (int k = 0; k < 32; k++) {
            ull ad[4], w_[4];
            #pragma unroll
            for (int i = 0; i < 4; i++) ad[i] = dup2(s.As[ty4 + i][k]);
            #pragma unroll
            for (int m = 0; m < 4; m++)
                w_[m] = *(const ull*)&s.Ws[k][m * 64 + tx * 2];
            #pragma unroll
            for (int i = 0; i < 4; i++)
                #pragma unroll
                for (int m = 0; m < 4; m++)
                    fma2(acc[i][m], ad[i], w_[m]);
        }
        __syncthreads();
    }
    #pragma unroll
    for (int i = 0; i < 4; i++) {
        size_t m = m0 + ty4 + i;
        #pragma unroll
        for (int m4 = 0; m4 < 4; m4++) {
            int n = n0 + m4 * 64 + tx * 2;
            float2 v = *(float2*)&acc[i][m4];
            v.x += __ldg(&b_ih[n])     + __ldg(&b_hh[n]);
            v.y += __ldg(&b_ih[n + 1]) + __ldg(&b_hh[n + 1]);
            *(float2*)&g_xw[m * Hz + n] = v;
        }
    }
}

// ---------------------------------------------------------------------------
// Persistent recurrent kernel: 512 steps, 128 CTAs x 256 threads.
// GEMM1: 4 n-tiles(256) x 32 k-slices(32).  GEMM2: 8 n-tiles(256) x 16 k-slices(64).
// ---------------------------------------------------------------------------
__global__ __launch_bounds__(256, 1) void rnn_persistent(
    const float* __restrict__ eps, const float* __restrict__ w_hh,
    const float* __restrict__ w_g, const float* __restrict__ b_g,
    float* __restrict__ o_seq, float* __restrict__ o_prob,
    float* __restrict__ o_mu, float* __restrict__ o_std)
{
    extern __shared__ unsigned char smraw[];
    SmemR& sm = *(SmemR*)smraw;
    const int cta = blockIdx.x;
    const int tid = threadIdx.x;
    const int tx8 = (tid & 31) * 8;
    const int ty8 = (tid >> 5) * 8;
    const int n01 = (cta & 3) * 256, kb1 = (cta >> 2) * 32;
    const int n02 = (cta & 7) * 256, kb2 = (cta >> 3) * 64;
    const size_t p1off = (size_t)(cta >> 2) * (Bz * Hz);
    const size_t p2off = (size_t)(cta >> 3) * (Bz * H2z);
    const float LPC = -0.5f * 1.8378770664093453f * (float)Hz;

    unsigned gen = *(volatile unsigned*)&g_epoch;

    // zero recurrent state (2 floats/thread)
    *(float2*)&g_h[(cta * 256 + tid) * 2] = make_float2(0.f, 0.f);

    // preload weight slices into SMEM (once)
    for (int e = tid; e < 256 * 32; e += 256) {
        int n = e >> 5, kk = e & 31;
        sm.Ws1[kk][n] = __ldg(&w_hh[(size_t)(n01 + n) * 1024 + kb1 + kk]);
    }
    for (int e = tid; e < 256 * 64; e += 256) {
        int n = e >> 6, kk = e & 63;
        sm.Ws2[kk][n] = __ldg(&w_g[(size_t)(n02 + n) * 1024 + kb2 + kk]);
    }
    grid_sync(gen);

    for (int t = 0; t < Tz; t++) {
        // ---- P0: o_prob(t-1) + GEMM1 partial: h @ w_hh^T -------------------
        if (t > 0 && cta < Bz && tid == 0)
            o_prob[cta * Tz + (t - 1)] =
                __ldcg(&g_lpp[cta][0]) + __ldcg(&g_lpp[cta][1]) + LPC;
        stage_A(sm.As2, g_h, kb1, 32, tid);
        __syncthreads();
        {
            ull acc[8][4] = {};
            gemm8x8(sm.As2, sm.Ws1, 32, acc, tx8, ty8);
            store8x8(g_p1 + p1off, Hz, n01, acc, tx8, ty8);
        }
        grid_sync(gen);

        // ---- P1: combine 32 partials + xw + tanh -> g_hrnn -----------------
        {
            int base = (cta * 256 + tid) * 2;          // b*1024 + j, j even
            int b = base >> 10, j = base & 1023;
            float2 v = __ldg((const float2*)&g_xw[((size_t)b * Tz + t) * Hz + j]);
            #pragma unroll
            for (int sl = 0; sl < 32; sl++) {
                float2 p = __ldcg((const float2*)&g_p1[(size_t)sl * (Bz * Hz) + base]);
                v.x += p.x; v.y += p.y;
            }
            *(float2*)&g_hrnn[base] = make_float2(tanhf(v.x), tanhf(v.y));
        }
        grid_sync(gen);

        // ---- P2: GEMM2 partial: h_rnn @ w_g^T ------------------------------
        stage_A(sm.As2, g_hrnn, kb2, 64, tid);
        __syncthreads();
        {
            ull acc[8][4] = {};
            gemm8x8(sm.As2, sm.Ws2, 64, acc, tx8, ty8);
            store8x8(g_p2 + p2off, H2z, n02, acc, tx8, ty8);
        }
        grid_sync(gen);

        // ---- P3: epilogue, half batch-row per CTA (2 j's per thread) -------
        {
            const int b = cta >> 1;
            const int j = (cta & 1) * 512 + tid * 2;
            float2 ss = __ldg((const float2*)&b_g[j]);
            float2 mu = __ldg((const float2*)&b_g[Hz + j]);
            #pragma unroll
            for (int sl = 0; sl < 16; sl++) {
                const float* p = g_p2 + (size_t)sl * (Bz * H2z) + (size_t)b * H2z;
                float2 a = __ldcg((const float2*)&p[j]);
                float2 c = __ldcg((const float2*)&p[Hz + j]);
                ss.x += a.x; ss.y += a.y;
                mu.x += c.x; mu.y += c.y;
            }
            float sdx = (ss.x > 20.f) ? ss.x : log1pf(expf(ss.x));
            float sdy = (ss.y > 20.f) ? ss.y : log1pf(expf(ss.y));
            float2 e = __ldg((const float2*)&eps[((size_t)b * Tz + t) * Hz + j]);
            float2 smp = make_float2(mu.x + sdx * e.x, mu.y + sdy * e.y);
            size_t o = ((size_t)b * Tz + t) * Hz + j;
            *(float2*)&o_seq[o] = smp;
            *(float2*)&o_mu[o]  = mu;
            *(float2*)&o_std[o] = make_float2(sdx, sdy);
            *(float2*)&g_h[b * Hz + j] = smp;

            float lp = -0.5f * (e.x * e.x + e.y * e.y) - logf(sdx) - logf(sdy);
            #pragma unroll
            for (int off = 16; off > 0; off >>= 1)
                lp += __shfl_xor_sync(0xffffffffu, lp, off);
            if ((tid & 31) == 0) sm.red[tid >> 5] = lp;
            __syncthreads();
            if (tid == 0) {
                float sum = 0.f;
                #pragma unroll
                for (int w = 0; w < 8; w++) sum += sm.red[w];
                g_lpp[b][cta & 1] = sum;
            }
        }
        grid_sync(gen);
    }

    if (cta < Bz && tid == 0)
        o_prob[cta * Tz + (Tz - 1)] =
            __ldcg(&g_lpp[cta][0]) + __ldcg(&g_lpp[cta][1]) + LPC;

    if (cta == 0 && tid == 0) *(volatile unsigned*)&g_epoch = gen;
}

// ---------------------------------------------------------------------------
extern "C" void kernel_launch(void* const* d_in, const int* in_sizes, int n_in,
                              void* d_out, int out_size)
{
    const float* x    = (const float*)d_in[0];
    const float* eps  = (const float*)d_in[1];
    const float* w_ih = (const float*)d_in[2];
    const float* w_hh = (const float*)d_in[3];
    const float* b_ih = (const float*)d_in[4];
    const float* b_hh = (const float*)d_in[5];
    const float* w_g  = (const float*)d_in[6];
    const float* b_g  = (const float*)d_in[7];

    float* out = (float*)d_out;
    float* o_seq  = out;
    float* o_prob = out + (size_t)Bz * Tz * Hz;
    float* o_mu   = o_prob + (size_t)Bz * Tz;
    float* o_std  = o_mu + (size_t)Bz * Tz * Hz;

    cudaFuncSetAttribute(rnn_persistent,
                         cudaFuncAttributeMaxDynamicSharedMemorySize,
                         (int)sizeof(SmemR));

    xw_kernel<<<dim3(4, 512), 512>>>(x, w_ih, b_ih, b_hh);
    rnn_persistent<<<NCTA, 256, sizeof(SmemR)>>>(eps, w_hh, w_g, b_g,
                                                 o_seq, o_prob, o_mu, o_std);
}